// round 14
// baseline (speedup 1.0000x reference)
#include <cuda_runtime.h>
#include <cuda_fp16.h>
#include <math.h>
#include <stdint.h>

#define BB 2
#define TT 2048
#define NH 16
#define NKV 4
#define HD 64
#define DMODEL 1024
#define NTOK (BB*TT)

// ---------------- precomputed fp16 operands (device globals, all hi-only) ---
__device__ __half g_xh[(size_t)NTOK*DMODEL];
__device__ __half g_wqh[(size_t)DMODEL*NH*HD];
__device__ __half g_wkh[(size_t)DMODEL*NKV*HD];
__device__ __half g_wvh[(size_t)DMODEL*NKV*HD];
__device__ __half g_woh[(size_t)NH*HD*DMODEL];
__device__ __half g_qh[(size_t)BB*NH*TT*HD];
__device__ __half g_kh[(size_t)BB*NKV*TT*HD];
__device__ __half g_vh[(size_t)BB*NKV*TT*HD];
__device__ __half g_aoh[(size_t)NTOK*DMODEL];

// ---------------------------------------------------------------------------
// helpers
// ---------------------------------------------------------------------------
__device__ __forceinline__ uint32_t sptr(const void* p) {
    return (uint32_t)__cvta_generic_to_shared(p);
}
__device__ __forceinline__ void ldsm4(uint32_t* r, uint32_t a) {
    asm volatile("ldmatrix.sync.aligned.m8n8.x4.shared.b16 {%0,%1,%2,%3},[%4];"
        : "=r"(r[0]), "=r"(r[1]), "=r"(r[2]), "=r"(r[3]) : "r"(a));
}
__device__ __forceinline__ void ldsm4t(uint32_t* r, uint32_t a) {
    asm volatile("ldmatrix.sync.aligned.m8n8.x4.trans.shared.b16 {%0,%1,%2,%3},[%4];"
        : "=r"(r[0]), "=r"(r[1]), "=r"(r[2]), "=r"(r[3]) : "r"(a));
}
__device__ __forceinline__ void mma16816(float* c, const uint32_t* a,
                                          uint32_t b0, uint32_t b1) {
    asm volatile("mma.sync.aligned.m16n8k16.row.col.f32.f16.f16.f32 "
        "{%0,%1,%2,%3},{%4,%5,%6,%7},{%8,%9},{%0,%1,%2,%3};"
        : "+f"(c[0]), "+f"(c[1]), "+f"(c[2]), "+f"(c[3])
        : "r"(a[0]), "r"(a[1]), "r"(a[2]), "r"(a[3]), "r"(b0), "r"(b1));
}
__device__ __forceinline__ uint32_t pkh(__half a, __half b) {
    return (uint32_t)__half_as_ushort(a) |
           ((uint32_t)__half_as_ushort(b) << 16);
}
__device__ __forceinline__ void cpa16(uint32_t dst, const void* src) {
    asm volatile("cp.async.cg.shared.global [%0],[%1],16;" :: "r"(dst), "l"(src));
}
#define CP_COMMIT asm volatile("cp.async.commit_group;")
#define CP_WAIT0  asm volatile("cp.async.wait_group 0;")

// ---------------------------------------------------------------------------
// fused convert kernel: all five fp32 arrays -> hi-only fp16, one launch
// ---------------------------------------------------------------------------
#define X4   (NTOK*DMODEL/4)
#define WQ4  (DMODEL*NH*HD/4)
#define WKV4 (DMODEL*NKV*HD/4)
#define TOT4 (X4 + WQ4 + 2*WKV4 + WQ4)

__global__ __launch_bounds__(256) void cvt_all_kernel(
    const float* __restrict__ x,  const float* __restrict__ wq,
    const float* __restrict__ wk, const float* __restrict__ wv,
    const float* __restrict__ wo)
{
    for (int i = blockIdx.x * 256 + threadIdx.x; i < TOT4; i += gridDim.x * 256) {
        const float* src; __half* dst; int j;
        if (i < X4)                        { j = i;                     src = x;  dst = g_xh; }
        else if (i < X4 + WQ4)             { j = i - X4;                src = wq; dst = g_wqh; }
        else if (i < X4 + WQ4 + WKV4)      { j = i - X4 - WQ4;          src = wk; dst = g_wkh; }
        else if (i < X4 + WQ4 + 2*WKV4)    { j = i - X4 - WQ4 - WKV4;   src = wv; dst = g_wvh; }
        else                               { j = i - X4 - WQ4 - 2*WKV4; src = wo; dst = g_woh; }
        float4 v = ((const float4*)src)[j];
        __half h0 = __float2half_rn(v.x), h1 = __float2half_rn(v.y);
        __half h2 = __float2half_rn(v.z), h3 = __float2half_rn(v.w);
        ((uint32_t*)(dst + (size_t)j*4))[0] = pkh(h0, h1);
        ((uint32_t*)(dst + (size_t)j*4))[1] = pkh(h2, h3);
    }
}

// ---------------------------------------------------------------------------
// GEMM smem geometry (fp16 elems): K-chunk 64, single-term.
// Per buffer: Ah (128x64@72) + Bh (64x128@136) = 17920 elems = 35840 B
// ---------------------------------------------------------------------------
#define GA_LD 72
#define GB_LD 136
#define GA_SZ (128*GA_LD)
#define GB_SZ (64*GB_LD)
#define GBUF  (GA_SZ + GB_SZ)
#define GEMM_SMEM_BYTES (2*GBUF*2)   // 71680

__device__ __forceinline__ void gemm_issue(
    uint32_t smbase, int buf,
    const __half* Ah, int lda, const __half* Bh, int ldb, int tid)
{
    uint32_t ab = smbase + (uint32_t)buf * (GBUF * 2);
    #pragma unroll
    for (int it = 0; it < 4; it++) {                 // A: 128 rows x 64 cols
        int u = it * 256 + tid; int r = u >> 3, c = (u & 7) * 8;
        cpa16(ab + (r * GA_LD + c) * 2, Ah + (size_t)r * lda + c);
    }
    uint32_t bb = ab + GA_SZ * 2;
    #pragma unroll
    for (int it = 0; it < 4; it++) {                 // B: 64 rows x 128 cols
        int u = it * 256 + tid; int r = u >> 4, c = (u & 15) * 8;
        cpa16(bb + (r * GB_LD + c) * 2, Bh + (size_t)r * ldb + c);
    }
}

// 4x2 warp tiling: warp (wy,wx) rows [wy*32,+32) x cols [wx*64,+64)
__device__ __forceinline__ void gemm_compute(
    const __half* base, int wy, int wx, int ln, float s[2][8][4])
{
    const __half* ah_ = base;
    const __half* bh_ = base + GA_SZ;
    #pragma unroll
    for (int kk = 0; kk < 4; kk++) {
        uint32_t ah4[2][4];
        const int acol = kk * 16 + ((ln >> 4) << 3);
        #pragma unroll
        for (int mf = 0; mf < 2; mf++) {
            const int arow = wy * 32 + mf * 16 + (ln & 15);
            ldsm4(ah4[mf], sptr(ah_ + arow * GA_LD + acol));
        }
        #pragma unroll
        for (int np = 0; np < 4; np++) {
            const int brow = kk * 16 + (ln & 7) + (((ln >> 3) & 1) << 3);
            const int bcol = wx * 64 + np * 16 + ((ln >> 4) << 3);
            uint32_t bh4[4];
            ldsm4t(bh4, sptr(bh_ + brow * GB_LD + bcol));
            mma16816(s[0][2*np],   ah4[0], bh4[0], bh4[1]);
            mma16816(s[0][2*np+1], ah4[0], bh4[2], bh4[3]);
            mma16816(s[1][2*np],   ah4[1], bh4[0], bh4[1]);
            mma16816(s[1][2*np+1], ah4[1], bh4[2], bh4[3]);
        }
    }
}

// ---------------------------------------------------------------------------
// Kernel A: QKV projection + RMSNorm + RoPE, single-term fp16.
// grid=(NTOK/128, 12)
// ---------------------------------------------------------------------------
__global__ void __launch_bounds__(256, 2) qkv_kernel(
    const float* __restrict__ cosb, const float* __restrict__ sinb,
    const float* __restrict__ qn_w, const float* __restrict__ kn_w)
{
    extern __shared__ __half smg[];
    const int tid = threadIdx.x, ln = tid & 31, wid = tid >> 5;
    const int wy = wid >> 1, wx = wid & 1;
    const int m0 = blockIdx.x * 128;
    const int nblk = blockIdx.y;

    const __half* Wh; int ldw, kind, hb;
    if (nblk < 8)       { Wh = g_wqh + nblk*128;      ldw = 1024; kind = 0; hb = nblk*2; }
    else if (nblk < 10) { Wh = g_wkh + (nblk-8)*128;  ldw = 256;  kind = 1; hb = (nblk-8)*2; }
    else                { Wh = g_wvh + (nblk-10)*128; ldw = 256;  kind = 2; hb = (nblk-10)*2; }

    const uint32_t smbase = sptr(smg);
    float s[2][8][4] = {};

    gemm_issue(smbase, 0, g_xh + (size_t)m0 * DMODEL, DMODEL, Wh, ldw, tid);
    CP_COMMIT;

    int buf = 0;
    for (int k0 = 0; k0 < DMODEL; k0 += 64) {
        CP_WAIT0;
        __syncthreads();
        if (k0 + 64 < DMODEL) {
            gemm_issue(smbase, buf ^ 1,
                       g_xh + (size_t)m0 * DMODEL + k0 + 64, DMODEL,
                       Wh + (size_t)(k0 + 64) * ldw, ldw, tid);
            CP_COMMIT;
        }
        gemm_compute(smg + buf * GBUF, wy, wx, ln, s);
        buf ^= 1;
    }

    const int q2 = (ln & 3) * 2;
    const int h = hb + wx;
    #pragma unroll
    for (int mf = 0; mf < 2; mf++) {
        #pragma unroll
        for (int hf = 0; hf < 2; hf++) {
            const int row = m0 + wy * 32 + mf * 16 + (ln >> 2) + hf * 8;
            const int b = row >> 11, tpos = row & 2047;
            if (kind != 2) {
                const float* nw = (kind == 0) ? qn_w : kn_w;
                float ss = 0.f;
                #pragma unroll
                for (int nf = 0; nf < 8; nf++) {
                    float v0 = s[mf][nf][hf*2], v1 = s[mf][nf][hf*2+1];
                    ss = fmaf(v0, v0, fmaf(v1, v1, ss));
                }
                ss += __shfl_xor_sync(0xffffffffu, ss, 1);
                ss += __shfl_xor_sync(0xffffffffu, ss, 2);
                const float inv = rsqrtf(ss * (1.f/64.f) + 1e-6f);
                #pragma unroll
                for (int j2 = 0; j2 < 4; j2++) {
                    #pragma unroll
                    for (int e = 0; e < 2; e++) {
                        const int hc = 8*j2 + q2 + e;
                        const int p = hf*2 + e;
                        float v1 = s[mf][j2][p]   * inv * nw[hc];
                        float v2 = s[mf][j2+4][p] * inv * nw[hc+32];
                        float cc = cosb[tpos*32 + hc], sn = sinb[tpos*32 + hc];
                        s[mf][j2][p]   = v1*cc - v2*sn;
                        s[mf][j2+4][p] = v2*cc + v1*sn;
                    }
                }
            }
            __half* dst = (kind == 0) ? g_qh : (kind == 1) ? g_kh : g_vh;
            size_t base = (kind == 0)
                ? (((size_t)(b*NH + h))*TT + tpos)*HD
                : (((size_t)(b*NKV + h))*TT + tpos)*HD;
            #pragma unroll
            for (int nf = 0; nf < 8; nf++) {
                const int d = 8*nf + q2;
                *(uint32_t*)(dst + base + d) =
                    pkh(__float2half_rn(s[mf][nf][hf*2]),
                        __float2half_rn(s[mf][nf][hf*2+1]));
            }
        }
    }
}

// ---------------------------------------------------------------------------
// Kernel B: causal flash attention — hi-only fp16, 2 CTAs/SM.
// grid=(T/128, B*H), 256 threads.
// ---------------------------------------------------------------------------
#define ATT_LD 72
#define ATT_ARR (128*ATT_LD)
#define ATT_STAGE (2*ATT_ARR)           // Kh, Vh
#define ATT_Q_OFF (2*ATT_STAGE)         // then Qh
#define ATTN_SMEM_BYTES ((2*ATT_STAGE + ATT_ARR)*2)   // 92160

__device__ __forceinline__ void kv_issue(uint32_t smbase, int stage,
    const __half* Kh, const __half* Vh, int tid)
{
    uint32_t sb = smbase + (uint32_t)stage * (ATT_STAGE * 2);
    #pragma unroll
    for (int it = 0; it < 4; it++) {
        int u = it * 256 + tid; int r = u >> 3, c = (u & 7) * 8;
        size_t off = (size_t)r * HD + c;
        uint32_t d = sb + (r * ATT_LD + c) * 2;
        cpa16(d,             Kh + off);
        cpa16(d + ATT_ARR*2, Vh + off);
    }
}

__global__ void __launch_bounds__(256, 2) attn_kernel()
{
    extern __shared__ __half smb[];
    const int tid = threadIdx.x, ln = tid & 31, wid = tid >> 5;
    const int qb = gridDim.x - 1 - blockIdx.x;
    const int bh = blockIdx.y;
    const int b = bh >> 4, h = bh & 15, kvh = h >> 2;
    const uint32_t smbase = sptr(smb);

    const __half* Qhg = g_qh + ((size_t)(b*NH + h)*TT + qb*128)*HD;
    const size_t kvbase = (size_t)(b*NKV + kvh)*TT*HD;

    {
        uint32_t qsb = smbase + ATT_Q_OFF * 2;
        #pragma unroll
        for (int it = 0; it < 4; it++) {
            int u = it * 256 + tid; int r = u >> 3, c = (u & 7) * 8;
            cpa16(qsb + (r * ATT_LD + c) * 2, Qhg + (size_t)r * HD + c);
        }
    }
    kv_issue(smbase, 0, g_kh + kvbase, g_vh + kvbase, tid);
    CP_COMMIT;

    const int mrow = wid * 16;
    const int q2 = (ln & 3) * 2;
    uint32_t qfh[4][4];
    float o[8][4] = {};
    float m_i[2] = {-1e30f, -1e30f}, l_i[2] = {0.f, 0.f};

    int buf = 0;
    for (int kb = 0; kb <= qb; kb++) {
        CP_WAIT0;
        __syncthreads();
        if (kb == 0) {
            const __half* Qh = smb + ATT_Q_OFF;
            #pragma unroll
            for (int kk = 0; kk < 4; kk++) {
                const int acol = kk * 16 + ((ln >> 4) << 3);
                ldsm4(qfh[kk], sptr(Qh + (mrow + (ln & 15)) * ATT_LD + acol));
            }
        }
        if (kb < qb) {
            size_t o1 = kvbase + (size_t)(kb+1)*128*HD;
            kv_issue(smbase, buf ^ 1, g_kh + o1, g_vh + o1, tid);
            CP_COMMIT;
        }

        const __half* Kh = smb + buf * ATT_STAGE;
        const __half* Vh = Kh + ATT_ARR;

        float s[16][4];
        #pragma unroll
        for (int f = 0; f < 16; f++) { s[f][0]=0.f; s[f][1]=0.f; s[f][2]=0.f; s[f][3]=0.f; }
        #pragma unroll
        for (int kk = 0; kk < 4; kk++) {
            const int kcol = kk*16 + (((ln >> 3) & 1) << 3);
            #pragma unroll
            for (int np2 = 0; np2 < 4; np2++) {
                const int npA = 2*np2, npB = 2*np2 + 1;
                const int krowA = npA*16 + (ln & 7) + ((ln >> 4) << 3);
                const int krowB = npB*16 + (ln & 7) + ((ln >> 4) << 3);
                uint32_t ba[4], bbq[4];
                ldsm4(ba,  sptr(Kh + krowA*ATT_LD + kcol));
                ldsm4(bbq, sptr(Kh + krowB*ATT_LD + kcol));
                mma16816(s[2*npA],   qfh[kk], ba[0],  ba[1]);
                mma16816(s[2*npA+1], qfh[kk], ba[2],  ba[3]);
                mma16816(s[2*npB],   qfh[kk], bbq[0], bbq[1]);
                mma16816(s[2*npB+1], qfh[kk], bbq[2], bbq[3]);
            }
        }

        const bool diag = (kb == qb);
        #pragma unroll
        for (int f = 0; f < 16; f++) {
            #pragma unroll
            for (int p = 0; p < 4; p++) {
                float sv = s[f][p] * 0.125f;
                if (diag) {
                    int ck = 8*f + q2 + (p & 1);
                    int rq = mrow + (ln >> 2) + (p >> 1)*8;
                    if (ck > rq) sv = -1e30f;
                }
                s[f][p] = sv;
            }
        }

        float ci[2];
        #pragma unroll
        for (int hf = 0; hf < 2; hf++) {
            float mx = -1e30f;
            #pragma unroll
            for (int f = 0; f < 16; f++)
                mx = fmaxf(mx, fmaxf(s[f][hf*2], s[f][hf*2+1]));
            mx = fmaxf(mx, __shfl_xor_sync(0xffffffffu, mx, 1));
            mx = fmaxf(mx, __shfl_xor_sync(0xffffffffu, mx, 2));
            float mnew = fmaxf(m_i[hf], mx);
            float c = __expf(m_i[hf] - mnew);
            float ps = 0.f;
            #pragma unroll
            for (int f = 0; f < 16; f++) {
                float p0 = __expf(s[f][hf*2]   - mnew);
                float p1 = __expf(s[f][hf*2+1] - mnew);
                s[f][hf*2] = p0; s[f][hf*2+1] = p1;
                ps += p0 + p1;
            }
            ps += __shfl_xor_sync(0xffffffffu, ps, 1);
            ps += __shfl_xor_sync(0xffffffffu, ps, 2);
            l_i[hf] = l_i[hf]*c + ps;
            m_i[hf] = mnew;
            ci[hf] = c;
        }
        #pragma unroll
        for (int f = 0; f < 8; f++) {
            o[f][0] *= ci[0]; o[f][1] *= ci[0];
            o[f][2] *= ci[1]; o[f][3] *= ci[1];
        }

        #pragma unroll
        for (int jj = 0; jj < 8; jj++) {
            uint32_t ph[4];
            #pragma unroll
            for (int t = 0; t < 4; t++) {
                const float* src = (t < 2) ? s[2*jj] : s[2*jj+1];
                ph[t] = pkh(__float2half_rn(src[(t & 1)*2]),
                            __float2half_rn(src[(t & 1)*2 + 1]));
            }
            const int vrow = jj*16 + (ln & 7) + (((ln >> 3) & 1) << 3);
            #pragma unroll
            for (int dp2 = 0; dp2 < 2; dp2++) {
                const int dpA = 2*dp2, dpB = dpA + 1;
                uint32_t va[4], vb[4];
                ldsm4t(va, sptr(Vh + vrow*ATT_LD + dpA*16 + ((ln >> 4) << 3)));
                ldsm4t(vb, sptr(Vh + vrow*ATT_LD + dpB*16 + ((ln >> 4) << 3)));
                mma16816(o[2*dpA],   ph, va[0], va[1]);
                mma16816(o[2*dpA+1], ph, va[2], va[3]);
                mma16816(o[2*dpB],   ph, vb[0], vb[1]);
                mma16816(o[2*dpB+1], ph, vb[2], vb[3]);
            }
        }
        buf ^= 1;
    }

    #pragma unroll
    for (int hf = 0; hf < 2; hf++) {
        const float inv = 1.0f / l_i[hf];
        const int row = qb*128 + mrow + (ln >> 2) + hf*8;
        const size_t t = (size_t)(b*TT + row);
        #pragma unroll
        for (int f = 0; f < 8; f++) {
            const int d = 8*f + q2;
            *(uint32_t*)(g_aoh + t*DMODEL + h*HD + d) =
                pkh(__float2half_rn(o[f][hf*2]*inv),
                    __float2half_rn(o[f][hf*2+1]*inv));
        }
    }
}

// ---------------------------------------------------------------------------
// Kernel C: output projection, single-term. grid=(NTOK/128, DM/128)
// ---------------------------------------------------------------------------
__global__ void __launch_bounds__(256, 2) out_kernel(float* __restrict__ out)
{
    extern __shared__ __half smg[];
    const int tid = threadIdx.x, ln = tid & 31, wid = tid >> 5;
    const int wy = wid >> 1, wx = wid & 1;
    const int m0 = blockIdx.x * 128, n0 = blockIdx.y * 128;
    const uint32_t smbase = sptr(smg);
    float s[2][8][4] = {};

    gemm_issue(smbase, 0, g_aoh + (size_t)m0 * DMODEL, DMODEL, g_woh + n0, DMODEL, tid);
    CP_COMMIT;

    int buf = 0;
    for (int k0 = 0; k0 < DMODEL; k0 += 64) {
        CP_WAIT0;
        __syncthreads();
        if (k0 + 64 < DMODEL) {
            gemm_issue(smbase, buf ^ 1,
                       g_aoh + (size_t)m0 * DMODEL + k0 + 64, DMODEL,
                       g_woh + (size_t)(k0 + 64) * DMODEL + n0, DMODEL, tid);
            CP_COMMIT;
        }
        gemm_compute(smg + buf * GBUF, wy, wx, ln, s);
        buf ^= 1;
    }

    const int q2 = (ln & 3) * 2;
    #pragma unroll
    for (int mf = 0; mf < 2; mf++) {
        #pragma unroll
        for (int hf = 0; hf < 2; hf++) {
            const int row = m0 + wy * 32 + mf * 16 + (ln >> 2) + hf * 8;
            #pragma unroll
            for (int nf = 0; nf < 8; nf++) {
                const int col = n0 + wx * 64 + 8*nf + q2;
                *(float2*)(out + (size_t)row * DMODEL + col) =
                    make_float2(s[mf][nf][hf*2], s[mf][nf][hf*2+1]);
            }
        }
    }
}

// ---------------------------------------------------------------------------
extern "C" void kernel_launch(void* const* d_in, const int* in_sizes, int n_in,
                              void* d_out, int out_size) {
    const float* x    = (const float*)d_in[0];
    const float* cosb = (const float*)d_in[1];
    const float* sinb = (const float*)d_in[2];
    const float* wq   = (const float*)d_in[3];
    const float* wk   = (const float*)d_in[4];
    const float* wv   = (const float*)d_in[5];
    const float* wo   = (const float*)d_in[6];
    const float* qn_w = (const float*)d_in[7];
    const float* kn_w = (const float*)d_in[8];
    float* out = (float*)d_out;

    static int smem_set = 0;
    if (!smem_set) {
        cudaFuncSetAttribute(qkv_kernel,
            cudaFuncAttributeMaxDynamicSharedMemorySize, GEMM_SMEM_BYTES);
        cudaFuncSetAttribute(attn_kernel,
            cudaFuncAttributeMaxDynamicSharedMemorySize, ATTN_SMEM_BYTES);
        cudaFuncSetAttribute(out_kernel,
            cudaFuncAttributeMaxDynamicSharedMemorySize, GEMM_SMEM_BYTES);
        smem_set = 1;
    }

    cvt_all_kernel<<<2048, 256>>>(x, wq, wk, wv, wo);

    dim3 gA(NTOK / 128, 12);
    qkv_kernel<<<gA, 256, GEMM_SMEM_BYTES>>>(cosb, sinb, qn_w, kn_w);

    dim3 gB(TT / 128, BB * NH);
    attn_kernel<<<gB, 256, ATTN_SMEM_BYTES>>>();

    dim3 gC(NTOK / 128, DMODEL / 128);
    out_kernel<<<gC, 256, GEMM_SMEM_BYTES>>>(out);
}

// round 15
// speedup vs baseline: 1.0687x; 1.0687x over previous
#include <cuda_runtime.h>
#include <cuda_fp16.h>
#include <math.h>
#include <stdint.h>

#define BB 2
#define TT 2048
#define NH 16
#define NKV 4
#define HD 64
#define DMODEL 1024
#define NTOK (BB*TT)

// ---------------- precomputed fp16 operands (device globals, all hi-only) ---
__device__ __half g_xh[(size_t)NTOK*DMODEL];
__device__ __half g_wqh[(size_t)DMODEL*NH*HD];
__device__ __half g_wkh[(size_t)DMODEL*NKV*HD];
__device__ __half g_wvh[(size_t)DMODEL*NKV*HD];
__device__ __half g_woh[(size_t)NH*HD*DMODEL];
__device__ __half g_qh[(size_t)BB*NH*TT*HD];
__device__ __half g_kh[(size_t)BB*NKV*TT*HD];
__device__ __half g_vh[(size_t)BB*NKV*TT*HD];
__device__ __half g_aoh[(size_t)NTOK*DMODEL];

// ---------------------------------------------------------------------------
// helpers
// ---------------------------------------------------------------------------
__device__ __forceinline__ uint32_t sptr(const void* p) {
    return (uint32_t)__cvta_generic_to_shared(p);
}
__device__ __forceinline__ void ldsm4(uint32_t* r, uint32_t a) {
    asm volatile("ldmatrix.sync.aligned.m8n8.x4.shared.b16 {%0,%1,%2,%3},[%4];"
        : "=r"(r[0]), "=r"(r[1]), "=r"(r[2]), "=r"(r[3]) : "r"(a));
}
__device__ __forceinline__ void ldsm4t(uint32_t* r, uint32_t a) {
    asm volatile("ldmatrix.sync.aligned.m8n8.x4.trans.shared.b16 {%0,%1,%2,%3},[%4];"
        : "=r"(r[0]), "=r"(r[1]), "=r"(r[2]), "=r"(r[3]) : "r"(a));
}
__device__ __forceinline__ void mma16816(float* c, const uint32_t* a,
                                          uint32_t b0, uint32_t b1) {
    asm volatile("mma.sync.aligned.m16n8k16.row.col.f32.f16.f16.f32 "
        "{%0,%1,%2,%3},{%4,%5,%6,%7},{%8,%9},{%0,%1,%2,%3};"
        : "+f"(c[0]), "+f"(c[1]), "+f"(c[2]), "+f"(c[3])
        : "r"(a[0]), "r"(a[1]), "r"(a[2]), "r"(a[3]), "r"(b0), "r"(b1));
}
__device__ __forceinline__ uint32_t pkh(__half a, __half b) {
    return (uint32_t)__half_as_ushort(a) |
           ((uint32_t)__half_as_ushort(b) << 16);
}
__device__ __forceinline__ void cpa16(uint32_t dst, const void* src) {
    asm volatile("cp.async.cg.shared.global [%0],[%1],16;" :: "r"(dst), "l"(src));
}
#define CP_COMMIT asm volatile("cp.async.commit_group;")
#define CP_WAIT0  asm volatile("cp.async.wait_group 0;")

// ---------------------------------------------------------------------------
// fused convert kernel: all five fp32 arrays -> hi-only fp16, one launch
// ---------------------------------------------------------------------------
#define X4   (NTOK*DMODEL/4)
#define WQ4  (DMODEL*NH*HD/4)
#define WKV4 (DMODEL*NKV*HD/4)
#define TOT4 (X4 + WQ4 + 2*WKV4 + WQ4)

__global__ __launch_bounds__(256) void cvt_all_kernel(
    const float* __restrict__ x,  const float* __restrict__ wq,
    const float* __restrict__ wk, const float* __restrict__ wv,
    const float* __restrict__ wo)
{
    for (int i = blockIdx.x * 256 + threadIdx.x; i < TOT4; i += gridDim.x * 256) {
        const float* src; __half* dst; int j;
        if (i < X4)                        { j = i;                     src = x;  dst = g_xh; }
        else if (i < X4 + WQ4)             { j = i - X4;                src = wq; dst = g_wqh; }
        else if (i < X4 + WQ4 + WKV4)      { j = i - X4 - WQ4;          src = wk; dst = g_wkh; }
        else if (i < X4 + WQ4 + 2*WKV4)    { j = i - X4 - WQ4 - WKV4;   src = wv; dst = g_wvh; }
        else                               { j = i - X4 - WQ4 - 2*WKV4; src = wo; dst = g_woh; }
        float4 v = ((const float4*)src)[j];
        __half h0 = __float2half_rn(v.x), h1 = __float2half_rn(v.y);
        __half h2 = __float2half_rn(v.z), h3 = __float2half_rn(v.w);
        ((uint32_t*)(dst + (size_t)j*4))[0] = pkh(h0, h1);
        ((uint32_t*)(dst + (size_t)j*4))[1] = pkh(h2, h3);
    }
}

// ---------------------------------------------------------------------------
// GEMM smem geometry (fp16 elems): K-chunk 64, single-term.
// Per buffer: Ah (128x64@72) + Bh (64x128@136) = 17920 elems = 35840 B
// ---------------------------------------------------------------------------
#define GA_LD 72
#define GB_LD 136
#define GA_SZ (128*GA_LD)
#define GB_SZ (64*GB_LD)
#define GBUF  (GA_SZ + GB_SZ)
#define GEMM_SMEM_BYTES (2*GBUF*2)   // 71680

__device__ __forceinline__ void gemm_issue(
    uint32_t smbase, int buf,
    const __half* Ah, int lda, const __half* Bh, int ldb, int tid)
{
    uint32_t ab = smbase + (uint32_t)buf * (GBUF * 2);
    #pragma unroll
    for (int it = 0; it < 4; it++) {                 // A: 128 rows x 64 cols
        int u = it * 256 + tid; int r = u >> 3, c = (u & 7) * 8;
        cpa16(ab + (r * GA_LD + c) * 2, Ah + (size_t)r * lda + c);
    }
    uint32_t bb = ab + GA_SZ * 2;
    #pragma unroll
    for (int it = 0; it < 4; it++) {                 // B: 64 rows x 128 cols
        int u = it * 256 + tid; int r = u >> 4, c = (u & 15) * 8;
        cpa16(bb + (r * GB_LD + c) * 2, Bh + (size_t)r * ldb + c);
    }
}

// 4x2 warp tiling: warp (wy,wx) rows [wy*32,+32) x cols [wx*64,+64)
__device__ __forceinline__ void gemm_compute(
    const __half* base, int wy, int wx, int ln, float s[2][8][4])
{
    const __half* ah_ = base;
    const __half* bh_ = base + GA_SZ;
    #pragma unroll
    for (int kk = 0; kk < 4; kk++) {
        uint32_t ah4[2][4];
        const int acol = kk * 16 + ((ln >> 4) << 3);
        #pragma unroll
        for (int mf = 0; mf < 2; mf++) {
            const int arow = wy * 32 + mf * 16 + (ln & 15);
            ldsm4(ah4[mf], sptr(ah_ + arow * GA_LD + acol));
        }
        #pragma unroll
        for (int np = 0; np < 4; np++) {
            const int brow = kk * 16 + (ln & 7) + (((ln >> 3) & 1) << 3);
            const int bcol = wx * 64 + np * 16 + ((ln >> 4) << 3);
            uint32_t bh4[4];
            ldsm4t(bh4, sptr(bh_ + brow * GB_LD + bcol));
            mma16816(s[0][2*np],   ah4[0], bh4[0], bh4[1]);
            mma16816(s[0][2*np+1], ah4[0], bh4[2], bh4[3]);
            mma16816(s[1][2*np],   ah4[1], bh4[0], bh4[1]);
            mma16816(s[1][2*np+1], ah4[1], bh4[2], bh4[3]);
        }
    }
}

// ---------------------------------------------------------------------------
// Kernel A: QKV projection + RMSNorm + RoPE, single-term fp16, k-chunk 64.
// grid=(NTOK/128, 12)
// ---------------------------------------------------------------------------
__global__ void __launch_bounds__(256, 2) qkv_kernel(
    const float* __restrict__ cosb, const float* __restrict__ sinb,
    const float* __restrict__ qn_w, const float* __restrict__ kn_w)
{
    extern __shared__ __half smg[];
    const int tid = threadIdx.x, ln = tid & 31, wid = tid >> 5;
    const int wy = wid >> 1, wx = wid & 1;
    const int m0 = blockIdx.x * 128;
    const int nblk = blockIdx.y;

    const __half* Wh; int ldw, kind, hb;
    if (nblk < 8)       { Wh = g_wqh + nblk*128;      ldw = 1024; kind = 0; hb = nblk*2; }
    else if (nblk < 10) { Wh = g_wkh + (nblk-8)*128;  ldw = 256;  kind = 1; hb = (nblk-8)*2; }
    else                { Wh = g_wvh + (nblk-10)*128; ldw = 256;  kind = 2; hb = (nblk-10)*2; }

    const uint32_t smbase = sptr(smg);
    float s[2][8][4] = {};

    gemm_issue(smbase, 0, g_xh + (size_t)m0 * DMODEL, DMODEL, Wh, ldw, tid);
    CP_COMMIT;

    int buf = 0;
    for (int k0 = 0; k0 < DMODEL; k0 += 64) {
        CP_WAIT0;
        __syncthreads();
        if (k0 + 64 < DMODEL) {
            gemm_issue(smbase, buf ^ 1,
                       g_xh + (size_t)m0 * DMODEL + k0 + 64, DMODEL,
                       Wh + (size_t)(k0 + 64) * ldw, ldw, tid);
            CP_COMMIT;
        }
        gemm_compute(smg + buf * GBUF, wy, wx, ln, s);
        buf ^= 1;
    }

    const int q2 = (ln & 3) * 2;
    const int h = hb + wx;
    #pragma unroll
    for (int mf = 0; mf < 2; mf++) {
        #pragma unroll
        for (int hf = 0; hf < 2; hf++) {
            const int row = m0 + wy * 32 + mf * 16 + (ln >> 2) + hf * 8;
            const int b = row >> 11, tpos = row & 2047;
            if (kind != 2) {
                const float* nw = (kind == 0) ? qn_w : kn_w;
                float ss = 0.f;
                #pragma unroll
                for (int nf = 0; nf < 8; nf++) {
                    float v0 = s[mf][nf][hf*2], v1 = s[mf][nf][hf*2+1];
                    ss = fmaf(v0, v0, fmaf(v1, v1, ss));
                }
                ss += __shfl_xor_sync(0xffffffffu, ss, 1);
                ss += __shfl_xor_sync(0xffffffffu, ss, 2);
                const float inv = rsqrtf(ss * (1.f/64.f) + 1e-6f);
                #pragma unroll
                for (int j2 = 0; j2 < 4; j2++) {
                    #pragma unroll
                    for (int e = 0; e < 2; e++) {
                        const int hc = 8*j2 + q2 + e;
                        const int p = hf*2 + e;
                        float v1 = s[mf][j2][p]   * inv * nw[hc];
                        float v2 = s[mf][j2+4][p] * inv * nw[hc+32];
                        float cc = cosb[tpos*32 + hc], sn = sinb[tpos*32 + hc];
                        s[mf][j2][p]   = v1*cc - v2*sn;
                        s[mf][j2+4][p] = v2*cc + v1*sn;
                    }
                }
            }
            __half* dst = (kind == 0) ? g_qh : (kind == 1) ? g_kh : g_vh;
            size_t base = (kind == 0)
                ? (((size_t)(b*NH + h))*TT + tpos)*HD
                : (((size_t)(b*NKV + h))*TT + tpos)*HD;
            #pragma unroll
            for (int nf = 0; nf < 8; nf++) {
                const int d = 8*nf + q2;
                *(uint32_t*)(dst + base + d) =
                    pkh(__float2half_rn(s[mf][nf][hf*2]),
                        __float2half_rn(s[mf][nf][hf*2+1]));
            }
        }
    }
}

// ---------------------------------------------------------------------------
// Kernel B: causal flash attention — hi-only fp16, 1 CTA/SM (R13 config).
// grid=(T/128, B*H), 256 threads.
// ---------------------------------------------------------------------------
#define ATT_LD 72
#define ATT_ARR (128*ATT_LD)
#define ATT_STAGE (2*ATT_ARR)           // Kh, Vh
#define ATT_Q_OFF (2*ATT_STAGE)         // then Qh
#define ATTN_SMEM_BYTES ((2*ATT_STAGE + ATT_ARR)*2)   // 92160

__device__ __forceinline__ void kv_issue(uint32_t smbase, int stage,
    const __half* Kh, const __half* Vh, int tid)
{
    uint32_t sb = smbase + (uint32_t)stage * (ATT_STAGE * 2);
    #pragma unroll
    for (int it = 0; it < 4; it++) {
        int u = it * 256 + tid; int r = u >> 3, c = (u & 7) * 8;
        size_t off = (size_t)r * HD + c;
        uint32_t d = sb + (r * ATT_LD + c) * 2;
        cpa16(d,             Kh + off);
        cpa16(d + ATT_ARR*2, Vh + off);
    }
}

__global__ void __launch_bounds__(256) attn_kernel()
{
    extern __shared__ __half smb[];
    const int tid = threadIdx.x, ln = tid & 31, wid = tid >> 5;
    const int qb = gridDim.x - 1 - blockIdx.x;
    const int bh = blockIdx.y;
    const int b = bh >> 4, h = bh & 15, kvh = h >> 2;
    const uint32_t smbase = sptr(smb);

    const __half* Qhg = g_qh + ((size_t)(b*NH + h)*TT + qb*128)*HD;
    const size_t kvbase = (size_t)(b*NKV + kvh)*TT*HD;

    {
        uint32_t qsb = smbase + ATT_Q_OFF * 2;
        #pragma unroll
        for (int it = 0; it < 4; it++) {
            int u = it * 256 + tid; int r = u >> 3, c = (u & 7) * 8;
            cpa16(qsb + (r * ATT_LD + c) * 2, Qhg + (size_t)r * HD + c);
        }
    }
    kv_issue(smbase, 0, g_kh + kvbase, g_vh + kvbase, tid);
    CP_COMMIT;

    const int mrow = wid * 16;
    const int q2 = (ln & 3) * 2;
    uint32_t qfh[4][4];
    float o[8][4] = {};
    float m_i[2] = {-1e30f, -1e30f}, l_i[2] = {0.f, 0.f};

    int buf = 0;
    for (int kb = 0; kb <= qb; kb++) {
        CP_WAIT0;
        __syncthreads();
        if (kb == 0) {
            const __half* Qh = smb + ATT_Q_OFF;
            #pragma unroll
            for (int kk = 0; kk < 4; kk++) {
                const int acol = kk * 16 + ((ln >> 4) << 3);
                ldsm4(qfh[kk], sptr(Qh + (mrow + (ln & 15)) * ATT_LD + acol));
            }
        }
        if (kb < qb) {
            size_t o1 = kvbase + (size_t)(kb+1)*128*HD;
            kv_issue(smbase, buf ^ 1, g_kh + o1, g_vh + o1, tid);
            CP_COMMIT;
        }

        const __half* Kh = smb + buf * ATT_STAGE;
        const __half* Vh = Kh + ATT_ARR;

        float s[16][4];
        #pragma unroll
        for (int f = 0; f < 16; f++) { s[f][0]=0.f; s[f][1]=0.f; s[f][2]=0.f; s[f][3]=0.f; }
        #pragma unroll
        for (int kk = 0; kk < 4; kk++) {
            const int kcol = kk*16 + (((ln >> 3) & 1) << 3);
            #pragma unroll
            for (int np2 = 0; np2 < 4; np2++) {
                const int npA = 2*np2, npB = 2*np2 + 1;
                const int krowA = npA*16 + (ln & 7) + ((ln >> 4) << 3);
                const int krowB = npB*16 + (ln & 7) + ((ln >> 4) << 3);
                uint32_t ba[4], bbq[4];
                ldsm4(ba,  sptr(Kh + krowA*ATT_LD + kcol));
                ldsm4(bbq, sptr(Kh + krowB*ATT_LD + kcol));
                mma16816(s[2*npA],   qfh[kk], ba[0],  ba[1]);
                mma16816(s[2*npA+1], qfh[kk], ba[2],  ba[3]);
                mma16816(s[2*npB],   qfh[kk], bbq[0], bbq[1]);
                mma16816(s[2*npB+1], qfh[kk], bbq[2], bbq[3]);
            }
        }

        const bool diag = (kb == qb);
        #pragma unroll
        for (int f = 0; f < 16; f++) {
            #pragma unroll
            for (int p = 0; p < 4; p++) {
                float sv = s[f][p] * 0.125f;
                if (diag) {
                    int ck = 8*f + q2 + (p & 1);
                    int rq = mrow + (ln >> 2) + (p >> 1)*8;
                    if (ck > rq) sv = -1e30f;
                }
                s[f][p] = sv;
            }
        }

        float ci[2];
        #pragma unroll
        for (int hf = 0; hf < 2; hf++) {
            float mx = -1e30f;
            #pragma unroll
            for (int f = 0; f < 16; f++)
                mx = fmaxf(mx, fmaxf(s[f][hf*2], s[f][hf*2+1]));
            mx = fmaxf(mx, __shfl_xor_sync(0xffffffffu, mx, 1));
            mx = fmaxf(mx, __shfl_xor_sync(0xffffffffu, mx, 2));
            float mnew = fmaxf(m_i[hf], mx);
            float c = __expf(m_i[hf] - mnew);
            float ps = 0.f;
            #pragma unroll
            for (int f = 0; f < 16; f++) {
                float p0 = __expf(s[f][hf*2]   - mnew);
                float p1 = __expf(s[f][hf*2+1] - mnew);
                s[f][hf*2] = p0; s[f][hf*2+1] = p1;
                ps += p0 + p1;
            }
            ps += __shfl_xor_sync(0xffffffffu, ps, 1);
            ps += __shfl_xor_sync(0xffffffffu, ps, 2);
            l_i[hf] = l_i[hf]*c + ps;
            m_i[hf] = mnew;
            ci[hf] = c;
        }
        #pragma unroll
        for (int f = 0; f < 8; f++) {
            o[f][0] *= ci[0]; o[f][1] *= ci[0];
            o[f][2] *= ci[1]; o[f][3] *= ci[1];
        }

        #pragma unroll
        for (int jj = 0; jj < 8; jj++) {
            uint32_t ph[4];
            #pragma unroll
            for (int t = 0; t < 4; t++) {
                const float* src = (t < 2) ? s[2*jj] : s[2*jj+1];
                ph[t] = pkh(__float2half_rn(src[(t & 1)*2]),
                            __float2half_rn(src[(t & 1)*2 + 1]));
            }
            const int vrow = jj*16 + (ln & 7) + (((ln >> 3) & 1) << 3);
            #pragma unroll
            for (int dp2 = 0; dp2 < 2; dp2++) {
                const int dpA = 2*dp2, dpB = dpA + 1;
                uint32_t va[4], vb[4];
                ldsm4t(va, sptr(Vh + vrow*ATT_LD + dpA*16 + ((ln >> 4) << 3)));
                ldsm4t(vb, sptr(Vh + vrow*ATT_LD + dpB*16 + ((ln >> 4) << 3)));
                mma16816(o[2*dpA],   ph, va[0], va[1]);
                mma16816(o[2*dpA+1], ph, va[2], va[3]);
                mma16816(o[2*dpB],   ph, vb[0], vb[1]);
                mma16816(o[2*dpB+1], ph, vb[2], vb[3]);
            }
        }
        buf ^= 1;
    }

    #pragma unroll
    for (int hf = 0; hf < 2; hf++) {
        const float inv = 1.0f / l_i[hf];
        const int row = qb*128 + mrow + (ln >> 2) + hf*8;
        const size_t t = (size_t)(b*TT + row);
        #pragma unroll
        for (int f = 0; f < 8; f++) {
            const int d = 8*f + q2;
            *(uint32_t*)(g_aoh + t*DMODEL + h*HD + d) =
                pkh(__float2half_rn(o[f][hf*2]*inv),
                    __float2half_rn(o[f][hf*2+1]*inv));
        }
    }
}

// ---------------------------------------------------------------------------
// Kernel C: output projection, single-term, k-chunk 64. grid=(NTOK/128, DM/128)
// ---------------------------------------------------------------------------
__global__ void __launch_bounds__(256, 2) out_kernel(float* __restrict__ out)
{
    extern __shared__ __half smg[];
    const int tid = threadIdx.x, ln = tid & 31, wid = tid >> 5;
    const int wy = wid >> 1, wx = wid & 1;
    const int m0 = blockIdx.x * 128, n0 = blockIdx.y * 128;
    const uint32_t smbase = sptr(smg);
    float s[2][8][4] = {};

    gemm_issue(smbase, 0, g_aoh + (size_t)m0 * DMODEL, DMODEL, g_woh + n0, DMODEL, tid);
    CP_COMMIT;

    int buf = 0;
    for (int k0 = 0; k0 < DMODEL; k0 += 64) {
        CP_WAIT0;
        __syncthreads();
        if (k0 + 64 < DMODEL) {
            gemm_issue(smbase, buf ^ 1,
                       g_aoh + (size_t)m0 * DMODEL + k0 + 64, DMODEL,
                       g_woh + (size_t)(k0 + 64) * DMODEL + n0, DMODEL, tid);
            CP_COMMIT;
        }
        gemm_compute(smg + buf * GBUF, wy, wx, ln, s);
        buf ^= 1;
    }

    const int q2 = (ln & 3) * 2;
    #pragma unroll
    for (int mf = 0; mf < 2; mf++) {
        #pragma unroll
        for (int hf = 0; hf < 2; hf++) {
            const int row = m0 + wy * 32 + mf * 16 + (ln >> 2) + hf * 8;
            #pragma unroll
            for (int nf = 0; nf < 8; nf++) {
                const int col = n0 + wx * 64 + 8*nf + q2;
                *(float2*)(out + (size_t)row * DMODEL + col) =
                    make_float2(s[mf][nf][hf*2], s[mf][nf][hf*2+1]);
            }
        }
    }
}

// ---------------------------------------------------------------------------
extern "C" void kernel_launch(void* const* d_in, const int* in_sizes, int n_in,
                              void* d_out, int out_size) {
    const float* x    = (const float*)d_in[0];
    const float* cosb = (const float*)d_in[1];
    const float* sinb = (const float*)d_in[2];
    const float* wq   = (const float*)d_in[3];
    const float* wk   = (const float*)d_in[4];
    const float* wv   = (const float*)d_in[5];
    const float* wo   = (const float*)d_in[6];
    const float* qn_w = (const float*)d_in[7];
    const float* kn_w = (const float*)d_in[8];
    float* out = (float*)d_out;

    static int smem_set = 0;
    if (!smem_set) {
        cudaFuncSetAttribute(qkv_kernel,
            cudaFuncAttributeMaxDynamicSharedMemorySize, GEMM_SMEM_BYTES);
        cudaFuncSetAttribute(attn_kernel,
            cudaFuncAttributeMaxDynamicSharedMemorySize, ATTN_SMEM_BYTES);
        cudaFuncSetAttribute(out_kernel,
            cudaFuncAttributeMaxDynamicSharedMemorySize, GEMM_SMEM_BYTES);
        smem_set = 1;
    }

    cvt_all_kernel<<<2048, 256>>>(x, wq, wk, wv, wo);

    dim3 gA(NTOK / 128, 12);
    qkv_kernel<<<gA, 256, GEMM_SMEM_BYTES>>>(cosb, sinb, qn_w, kn_w);

    dim3 gB(TT / 128, BB * NH);
    attn_kernel<<<gB, 256, ATTN_SMEM_BYTES>>>();

    dim3 gC(NTOK / 128, DMODEL / 128);
    out_kernel<<<gC, 256, GEMM_SMEM_BYTES>>>(out);
}

// round 16
// speedup vs baseline: 1.1353x; 1.0624x over previous
#include <cuda_runtime.h>
#include <cuda_fp16.h>
#include <math.h>
#include <stdint.h>

#define BB 2
#define TT 2048
#define NH 16
#define NKV 4
#define HD 64
#define DMODEL 1024
#define NTOK (BB*TT)
#define SCALE_LOG2E 0.1803368801111357f   // 0.125 * log2(e)

// ---------------- precomputed fp16 operands (device globals, all hi-only) ---
__device__ __half g_xh[(size_t)NTOK*DMODEL];
__device__ __half g_wqh[(size_t)DMODEL*NH*HD];
__device__ __half g_wkh[(size_t)DMODEL*NKV*HD];
__device__ __half g_wvh[(size_t)DMODEL*NKV*HD];
__device__ __half g_woh[(size_t)NH*HD*DMODEL];
__device__ __half g_qh[(size_t)BB*NH*TT*HD];
__device__ __half g_kh[(size_t)BB*NKV*TT*HD];
__device__ __half g_vh[(size_t)BB*NKV*TT*HD];
__device__ __half g_aoh[(size_t)NTOK*DMODEL];

// ---------------------------------------------------------------------------
// helpers
// ---------------------------------------------------------------------------
__device__ __forceinline__ uint32_t sptr(const void* p) {
    return (uint32_t)__cvta_generic_to_shared(p);
}
__device__ __forceinline__ void ldsm4(uint32_t* r, uint32_t a) {
    asm volatile("ldmatrix.sync.aligned.m8n8.x4.shared.b16 {%0,%1,%2,%3},[%4];"
        : "=r"(r[0]), "=r"(r[1]), "=r"(r[2]), "=r"(r[3]) : "r"(a));
}
__device__ __forceinline__ void ldsm4t(uint32_t* r, uint32_t a) {
    asm volatile("ldmatrix.sync.aligned.m8n8.x4.trans.shared.b16 {%0,%1,%2,%3},[%4];"
        : "=r"(r[0]), "=r"(r[1]), "=r"(r[2]), "=r"(r[3]) : "r"(a));
}
__device__ __forceinline__ void mma16816(float* c, const uint32_t* a,
                                          uint32_t b0, uint32_t b1) {
    asm volatile("mma.sync.aligned.m16n8k16.row.col.f32.f16.f16.f32 "
        "{%0,%1,%2,%3},{%4,%5,%6,%7},{%8,%9},{%0,%1,%2,%3};"
        : "+f"(c[0]), "+f"(c[1]), "+f"(c[2]), "+f"(c[3])
        : "r"(a[0]), "r"(a[1]), "r"(a[2]), "r"(a[3]), "r"(b0), "r"(b1));
}
__device__ __forceinline__ float ex2(float x) {
    float r;
    asm("ex2.approx.f32 %0, %1;" : "=f"(r) : "f"(x));
    return r;
}
__device__ __forceinline__ uint32_t pk2(float a, float b) {
    __half2 h = __floats2half2_rn(a, b);
    return *(uint32_t*)&h;
}
__device__ __forceinline__ void cpa16(uint32_t dst, const void* src) {
    asm volatile("cp.async.cg.shared.global [%0],[%1],16;" :: "r"(dst), "l"(src));
}
#define CP_COMMIT asm volatile("cp.async.commit_group;")
#define CP_WAIT0  asm volatile("cp.async.wait_group 0;")

// ---------------------------------------------------------------------------
// fused convert kernel: all five fp32 arrays -> hi-only fp16, one launch
// ---------------------------------------------------------------------------
#define X4   (NTOK*DMODEL/4)
#define WQ4  (DMODEL*NH*HD/4)
#define WKV4 (DMODEL*NKV*HD/4)
#define TOT4 (X4 + WQ4 + 2*WKV4 + WQ4)

__global__ __launch_bounds__(256) void cvt_all_kernel(
    const float* __restrict__ x,  const float* __restrict__ wq,
    const float* __restrict__ wk, const float* __restrict__ wv,
    const float* __restrict__ wo)
{
    for (int i = blockIdx.x * 256 + threadIdx.x; i < TOT4; i += gridDim.x * 256) {
        const float* src; __half* dst; int j;
        if (i < X4)                        { j = i;                     src = x;  dst = g_xh; }
        else if (i < X4 + WQ4)             { j = i - X4;                src = wq; dst = g_wqh; }
        else if (i < X4 + WQ4 + WKV4)      { j = i - X4 - WQ4;          src = wk; dst = g_wkh; }
        else if (i < X4 + WQ4 + 2*WKV4)    { j = i - X4 - WQ4 - WKV4;   src = wv; dst = g_wvh; }
        else                               { j = i - X4 - WQ4 - 2*WKV4; src = wo; dst = g_woh; }
        float4 v = ((const float4*)src)[j];
        ((uint32_t*)(dst + (size_t)j*4))[0] = pk2(v.x, v.y);
        ((uint32_t*)(dst + (size_t)j*4))[1] = pk2(v.z, v.w);
    }
}

// ---------------------------------------------------------------------------
// GEMM smem geometry (fp16 elems): K-chunk 64, single-term.
// ---------------------------------------------------------------------------
#define GA_LD 72
#define GB_LD 136
#define GA_SZ (128*GA_LD)
#define GB_SZ (64*GB_LD)
#define GBUF  (GA_SZ + GB_SZ)
#define GEMM_SMEM_BYTES (2*GBUF*2)   // 71680

__device__ __forceinline__ void gemm_issue(
    uint32_t smbase, int buf,
    const __half* Ah, int lda, const __half* Bh, int ldb, int tid)
{
    uint32_t ab = smbase + (uint32_t)buf * (GBUF * 2);
    #pragma unroll
    for (int it = 0; it < 4; it++) {                 // A: 128 rows x 64 cols
        int u = it * 256 + tid; int r = u >> 3, c = (u & 7) * 8;
        cpa16(ab + (r * GA_LD + c) * 2, Ah + (size_t)r * lda + c);
    }
    uint32_t bb = ab + GA_SZ * 2;
    #pragma unroll
    for (int it = 0; it < 4; it++) {                 // B: 64 rows x 128 cols
        int u = it * 256 + tid; int r = u >> 4, c = (u & 15) * 8;
        cpa16(bb + (r * GB_LD + c) * 2, Bh + (size_t)r * ldb + c);
    }
}

__device__ __forceinline__ void gemm_compute(
    const __half* base, int wy, int wx, int ln, float s[2][8][4])
{
    const __half* ah_ = base;
    const __half* bh_ = base + GA_SZ;
    #pragma unroll
    for (int kk = 0; kk < 4; kk++) {
        uint32_t ah4[2][4];
        const int acol = kk * 16 + ((ln >> 4) << 3);
        #pragma unroll
        for (int mf = 0; mf < 2; mf++) {
            const int arow = wy * 32 + mf * 16 + (ln & 15);
            ldsm4(ah4[mf], sptr(ah_ + arow * GA_LD + acol));
        }
        #pragma unroll
        for (int np = 0; np < 4; np++) {
            const int brow = kk * 16 + (ln & 7) + (((ln >> 3) & 1) << 3);
            const int bcol = wx * 64 + np * 16 + ((ln >> 4) << 3);
            uint32_t bh4[4];
            ldsm4t(bh4, sptr(bh_ + brow * GB_LD + bcol));
            mma16816(s[0][2*np],   ah4[0], bh4[0], bh4[1]);
            mma16816(s[0][2*np+1], ah4[0], bh4[2], bh4[3]);
            mma16816(s[1][2*np],   ah4[1], bh4[0], bh4[1]);
            mma16816(s[1][2*np+1], ah4[1], bh4[2], bh4[3]);
        }
    }
}

// ---------------------------------------------------------------------------
// Kernel A: QKV projection + RMSNorm + RoPE, single-term fp16, k-chunk 64.
// grid=(NTOK/128, 12)
// ---------------------------------------------------------------------------
__global__ void __launch_bounds__(256, 2) qkv_kernel(
    const float* __restrict__ cosb, const float* __restrict__ sinb,
    const float* __restrict__ qn_w, const float* __restrict__ kn_w)
{
    extern __shared__ __half smg[];
    const int tid = threadIdx.x, ln = tid & 31, wid = tid >> 5;
    const int wy = wid >> 1, wx = wid & 1;
    const int m0 = blockIdx.x * 128;
    const int nblk = blockIdx.y;

    const __half* Wh; int ldw, kind, hb;
    if (nblk < 8)       { Wh = g_wqh + nblk*128;      ldw = 1024; kind = 0; hb = nblk*2; }
    else if (nblk < 10) { Wh = g_wkh + (nblk-8)*128;  ldw = 256;  kind = 1; hb = (nblk-8)*2; }
    else                { Wh = g_wvh + (nblk-10)*128; ldw = 256;  kind = 2; hb = (nblk-10)*2; }

    const uint32_t smbase = sptr(smg);
    float s[2][8][4] = {};

    gemm_issue(smbase, 0, g_xh + (size_t)m0 * DMODEL, DMODEL, Wh, ldw, tid);
    CP_COMMIT;

    int buf = 0;
    for (int k0 = 0; k0 < DMODEL; k0 += 64) {
        CP_WAIT0;
        __syncthreads();
        if (k0 + 64 < DMODEL) {
            gemm_issue(smbase, buf ^ 1,
                       g_xh + (size_t)m0 * DMODEL + k0 + 64, DMODEL,
                       Wh + (size_t)(k0 + 64) * ldw, ldw, tid);
            CP_COMMIT;
        }
        gemm_compute(smg + buf * GBUF, wy, wx, ln, s);
        buf ^= 1;
    }

    const int q2 = (ln & 3) * 2;
    const int h = hb + wx;
    #pragma unroll
    for (int mf = 0; mf < 2; mf++) {
        #pragma unroll
        for (int hf = 0; hf < 2; hf++) {
            const int row = m0 + wy * 32 + mf * 16 + (ln >> 2) + hf * 8;
            const int b = row >> 11, tpos = row & 2047;
            if (kind != 2) {
                const float* nw = (kind == 0) ? qn_w : kn_w;
                float ss = 0.f;
                #pragma unroll
                for (int nf = 0; nf < 8; nf++) {
                    float v0 = s[mf][nf][hf*2], v1 = s[mf][nf][hf*2+1];
                    ss = fmaf(v0, v0, fmaf(v1, v1, ss));
                }
                ss += __shfl_xor_sync(0xffffffffu, ss, 1);
                ss += __shfl_xor_sync(0xffffffffu, ss, 2);
                const float inv = rsqrtf(ss * (1.f/64.f) + 1e-6f);
                #pragma unroll
                for (int j2 = 0; j2 < 4; j2++) {
                    #pragma unroll
                    for (int e = 0; e < 2; e++) {
                        const int hc = 8*j2 + q2 + e;
                        const int p = hf*2 + e;
                        float v1 = s[mf][j2][p]   * inv * nw[hc];
                        float v2 = s[mf][j2+4][p] * inv * nw[hc+32];
                        float cc = cosb[tpos*32 + hc], sn = sinb[tpos*32 + hc];
                        s[mf][j2][p]   = v1*cc - v2*sn;
                        s[mf][j2+4][p] = v2*cc + v1*sn;
                    }
                }
            }
            __half* dst = (kind == 0) ? g_qh : (kind == 1) ? g_kh : g_vh;
            size_t base = (kind == 0)
                ? (((size_t)(b*NH + h))*TT + tpos)*HD
                : (((size_t)(b*NKV + h))*TT + tpos)*HD;
            #pragma unroll
            for (int nf = 0; nf < 8; nf++) {
                const int d = 8*nf + q2;
                *(uint32_t*)(dst + base + d) = pk2(s[mf][nf][hf*2], s[mf][nf][hf*2+1]);
            }
        }
    }
}

// ---------------------------------------------------------------------------
// Kernel B: causal flash attention — hi-only fp16, exp2-domain softmax.
// grid=(T/128, B*H), 256 threads, 1 CTA/SM.
// ---------------------------------------------------------------------------
#define ATT_LD 72
#define ATT_ARR (128*ATT_LD)
#define ATT_STAGE (2*ATT_ARR)           // Kh, Vh
#define ATT_Q_OFF (2*ATT_STAGE)         // then Qh
#define ATTN_SMEM_BYTES ((2*ATT_STAGE + ATT_ARR)*2)   // 92160

__device__ __forceinline__ void kv_issue(uint32_t smbase, int stage,
    const __half* Kh, const __half* Vh, int tid)
{
    uint32_t sb = smbase + (uint32_t)stage * (ATT_STAGE * 2);
    #pragma unroll
    for (int it = 0; it < 4; it++) {
        int u = it * 256 + tid; int r = u >> 3, c = (u & 7) * 8;
        size_t off = (size_t)r * HD + c;
        uint32_t d = sb + (r * ATT_LD + c) * 2;
        cpa16(d,             Kh + off);
        cpa16(d + ATT_ARR*2, Vh + off);
    }
}

__global__ void __launch_bounds__(256) attn_kernel()
{
    extern __shared__ __half smb[];
    const int tid = threadIdx.x, ln = tid & 31, wid = tid >> 5;
    const int qb = gridDim.x - 1 - blockIdx.x;
    const int bh = blockIdx.y;
    const int b = bh >> 4, h = bh & 15, kvh = h >> 2;
    const uint32_t smbase = sptr(smb);

    const __half* Qhg = g_qh + ((size_t)(b*NH + h)*TT + qb*128)*HD;
    const size_t kvbase = (size_t)(b*NKV + kvh)*TT*HD;

    {
        uint32_t qsb = smbase + ATT_Q_OFF * 2;
        #pragma unroll
        for (int it = 0; it < 4; it++) {
            int u = it * 256 + tid; int r = u >> 3, c = (u & 7) * 8;
            cpa16(qsb + (r * ATT_LD + c) * 2, Qhg + (size_t)r * HD + c);
        }
    }
    kv_issue(smbase, 0, g_kh + kvbase, g_vh + kvbase, tid);
    CP_COMMIT;

    const int mrow = wid * 16;
    const int q2 = (ln & 3) * 2;
    uint32_t qfh[4][4];
    float o[8][4] = {};
    // m_i, l_i kept in log2 domain
    float m_i[2] = {-1e30f, -1e30f}, l_i[2] = {0.f, 0.f};

    int buf = 0;
    for (int kb = 0; kb <= qb; kb++) {
        CP_WAIT0;
        __syncthreads();
        if (kb == 0) {
            const __half* Qh = smb + ATT_Q_OFF;
            #pragma unroll
            for (int kk = 0; kk < 4; kk++) {
                const int acol = kk * 16 + ((ln >> 4) << 3);
                ldsm4(qfh[kk], sptr(Qh + (mrow + (ln & 15)) * ATT_LD + acol));
            }
        }
        if (kb < qb) {
            size_t o1 = kvbase + (size_t)(kb+1)*128*HD;
            kv_issue(smbase, buf ^ 1, g_kh + o1, g_vh + o1, tid);
            CP_COMMIT;
        }

        const __half* Kh = smb + buf * ATT_STAGE;
        const __half* Vh = Kh + ATT_ARR;

        float s[16][4];
        #pragma unroll
        for (int f = 0; f < 16; f++) { s[f][0]=0.f; s[f][1]=0.f; s[f][2]=0.f; s[f][3]=0.f; }
        #pragma unroll
        for (int kk = 0; kk < 4; kk++) {
            const int kcol = kk*16 + (((ln >> 3) & 1) << 3);
            #pragma unroll
            for (int np2 = 0; np2 < 4; np2++) {
                const int npA = 2*np2, npB = 2*np2 + 1;
                const int krowA = npA*16 + (ln & 7) + ((ln >> 4) << 3);
                const int krowB = npB*16 + (ln & 7) + ((ln >> 4) << 3);
                uint32_t ba[4], bbq[4];
                ldsm4(ba,  sptr(Kh + krowA*ATT_LD + kcol));
                ldsm4(bbq, sptr(Kh + krowB*ATT_LD + kcol));
                mma16816(s[2*npA],   qfh[kk], ba[0],  ba[1]);
                mma16816(s[2*npA+1], qfh[kk], ba[2],  ba[3]);
                mma16816(s[2*npB],   qfh[kk], bbq[0], bbq[1]);
                mma16816(s[2*npB+1], qfh[kk], bbq[2], bbq[3]);
            }
        }

        // scale into exp2 domain + causal mask
        const bool diag = (kb == qb);
        #pragma unroll
        for (int f = 0; f < 16; f++) {
            #pragma unroll
            for (int p = 0; p < 4; p++) {
                float sv = s[f][p] * SCALE_LOG2E;
                if (diag) {
                    int ck = 8*f + q2 + (p & 1);
                    int rq = mrow + (ln >> 2) + (p >> 1)*8;
                    if (ck > rq) sv = -1e30f;
                }
                s[f][p] = sv;
            }
        }

        float ci[2];
        #pragma unroll
        for (int hf = 0; hf < 2; hf++) {
            float mx = -1e30f;
            #pragma unroll
            for (int f = 0; f < 16; f++)
                mx = fmaxf(mx, fmaxf(s[f][hf*2], s[f][hf*2+1]));
            mx = fmaxf(mx, __shfl_xor_sync(0xffffffffu, mx, 1));
            mx = fmaxf(mx, __shfl_xor_sync(0xffffffffu, mx, 2));
            float mnew = fmaxf(m_i[hf], mx);
            float c = ex2(m_i[hf] - mnew);
            float ps = 0.f;
            #pragma unroll
            for (int f = 0; f < 16; f++) {
                float p0 = ex2(s[f][hf*2]   - mnew);
                float p1 = ex2(s[f][hf*2+1] - mnew);
                s[f][hf*2] = p0; s[f][hf*2+1] = p1;
                ps += p0 + p1;
            }
            ps += __shfl_xor_sync(0xffffffffu, ps, 1);
            ps += __shfl_xor_sync(0xffffffffu, ps, 2);
            l_i[hf] = l_i[hf]*c + ps;
            m_i[hf] = mnew;
            ci[hf] = c;
        }
        #pragma unroll
        for (int f = 0; f < 8; f++) {
            o[f][0] *= ci[0]; o[f][1] *= ci[0];
            o[f][2] *= ci[1]; o[f][3] *= ci[1];
        }

        // O += P V — P hi only, paired f16x2 conversion
        #pragma unroll
        for (int jj = 0; jj < 8; jj++) {
            uint32_t ph[4];
            #pragma unroll
            for (int t = 0; t < 4; t++) {
                const float* src = (t < 2) ? s[2*jj] : s[2*jj+1];
                ph[t] = pk2(src[(t & 1)*2], src[(t & 1)*2 + 1]);
            }
            const int vrow = jj*16 + (ln & 7) + (((ln >> 3) & 1) << 3);
            #pragma unroll
            for (int dp2 = 0; dp2 < 2; dp2++) {
                const int dpA = 2*dp2, dpB = dpA + 1;
                uint32_t va[4], vb[4];
                ldsm4t(va, sptr(Vh + vrow*ATT_LD + dpA*16 + ((ln >> 4) << 3)));
                ldsm4t(vb, sptr(Vh + vrow*ATT_LD + dpB*16 + ((ln >> 4) << 3)));
                mma16816(o[2*dpA],   ph, va[0], va[1]);
                mma16816(o[2*dpA+1], ph, va[2], va[3]);
                mma16816(o[2*dpB],   ph, vb[0], vb[1]);
                mma16816(o[2*dpB+1], ph, vb[2], vb[3]);
            }
        }
        buf ^= 1;
    }

    #pragma unroll
    for (int hf = 0; hf < 2; hf++) {
        const float inv = 1.0f / l_i[hf];
        const int row = qb*128 + mrow + (ln >> 2) + hf*8;
        const size_t t = (size_t)(b*TT + row);
        #pragma unroll
        for (int f = 0; f < 8; f++) {
            const int d = 8*f + q2;
            *(uint32_t*)(g_aoh + t*DMODEL + h*HD + d) =
                pk2(o[f][hf*2]*inv, o[f][hf*2+1]*inv);
        }
    }
}

// ---------------------------------------------------------------------------
// Kernel C: output projection, single-term, k-chunk 64. grid=(NTOK/128, DM/128)
// ---------------------------------------------------------------------------
__global__ void __launch_bounds__(256, 2) out_kernel(float* __restrict__ out)
{
    extern __shared__ __half smg[];
    const int tid = threadIdx.x, ln = tid & 31, wid = tid >> 5;
    const int wy = wid >> 1, wx = wid & 1;
    const int m0 = blockIdx.x * 128, n0 = blockIdx.y * 128;
    const uint32_t smbase = sptr(smg);
    float s[2][8][4] = {};

    gemm_issue(smbase, 0, g_aoh + (size_t)m0 * DMODEL, DMODEL, g_woh + n0, DMODEL, tid);
    CP_COMMIT;

    int buf = 0;
    for (int k0 = 0; k0 < DMODEL; k0 += 64) {
        CP_WAIT0;
        __syncthreads();
        if (k0 + 64 < DMODEL) {
            gemm_issue(smbase, buf ^ 1,
                       g_aoh + (size_t)m0 * DMODEL + k0 + 64, DMODEL,
                       g_woh + (size_t)(k0 + 64) * DMODEL + n0, DMODEL, tid);
            CP_COMMIT;
        }
        gemm_compute(smg + buf * GBUF, wy, wx, ln, s);
        buf ^= 1;
    }

    const int q2 = (ln & 3) * 2;
    #pragma unroll
    for (int mf = 0; mf < 2; mf++) {
        #pragma unroll
        for (int hf = 0; hf < 2; hf++) {
            const int row = m0 + wy * 32 + mf * 16 + (ln >> 2) + hf * 8;
            #pragma unroll
            for (int nf = 0; nf < 8; nf++) {
                const int col = n0 + wx * 64 + 8*nf + q2;
                *(float2*)(out + (size_t)row * DMODEL + col) =
                    make_float2(s[mf][nf][hf*2], s[mf][nf][hf*2+1]);
            }
        }
    }
}

// ---------------------------------------------------------------------------
extern "C" void kernel_launch(void* const* d_in, const int* in_sizes, int n_in,
                              void* d_out, int out_size) {
    const float* x    = (const float*)d_in[0];
    const float* cosb = (const float*)d_in[1];
    const float* sinb = (const float*)d_in[2];
    const float* wq   = (const float*)d_in[3];
    const float* wk   = (const float*)d_in[4];
    const float* wv   = (const float*)d_in[5];
    const float* wo   = (const float*)d_in[6];
    const float* qn_w = (const float*)d_in[7];
    const float* kn_w = (const float*)d_in[8];
    float* out = (float*)d_out;

    static int smem_set = 0;
    if (!smem_set) {
        cudaFuncSetAttribute(qkv_kernel,
            cudaFuncAttributeMaxDynamicSharedMemorySize, GEMM_SMEM_BYTES);
        cudaFuncSetAttribute(attn_kernel,
            cudaFuncAttributeMaxDynamicSharedMemorySize, ATTN_SMEM_BYTES);
        cudaFuncSetAttribute(out_kernel,
            cudaFuncAttributeMaxDynamicSharedMemorySize, GEMM_SMEM_BYTES);
        smem_set = 1;
    }

    cvt_all_kernel<<<2048, 256>>>(x, wq, wk, wv, wo);

    dim3 gA(NTOK / 128, 12);
    qkv_kernel<<<gA, 256, GEMM_SMEM_BYTES>>>(cosb, sinb, qn_w, kn_w);

    dim3 gB(TT / 128, BB * NH);
    attn_kernel<<<gB, 256, ATTN_SMEM_BYTES>>>();

    dim3 gC(NTOK / 128, DMODEL / 128);
    out_kernel<<<gC, 256, GEMM_SMEM_BYTES>>>(out);
}